// round 1
// baseline (speedup 1.0000x reference)
#include <cuda_runtime.h>

// ---------------------------------------------------------------------------
// SparseConvNet on GB300 — round 0: list-compacted fp32 conv with f32x2 FFMA2
// Layouts: all intermediate feature volumes are channels-last [z][y][x][c].
// Masked-out voxels are never written; __device__ globals are zero-initialized
// at module load, so they stay exactly 0.0f forever (deterministic replays).
// ---------------------------------------------------------------------------

#define N0 (128*128*128)
#define N1 (64*64*64)

typedef unsigned long long u64;

__device__ float g_h0a[16u * N0];   // stage1 out (128^3 x 16)
__device__ float g_h0b[16u * N0];   // stage2 out
__device__ float g_h1a[32u * N1];   // stage3 out (64^3 x 32)
__device__ float g_h1b[32u * N1];   // stage4 out
__device__ float g_h1c[32u * N1];   // stage5 out
__device__ int   g_list0[N0];
__device__ int   g_list1[N1];
__device__ int   g_cnt[2];

// ---- packed f32x2 helpers (sm_100+): 2 fp32 FMAs per issue slot -----------
__device__ __forceinline__ u64 pack2(float lo, float hi) {
    u64 d; asm("mov.b64 %0, {%1, %2};" : "=l"(d) : "f"(lo), "f"(hi)); return d;
}
__device__ __forceinline__ void unpack2(u64 v, float& lo, float& hi) {
    asm("mov.b64 {%0, %1}, %2;" : "=f"(lo), "=f"(hi) : "l"(v));
}
__device__ __forceinline__ u64 ffma2(u64 a, u64 b, u64 c) {
    u64 r; asm("fma.rn.f32x2 %0, %1, %2, %3;" : "=l"(r) : "l"(a), "l"(b), "l"(c));
    return r;
}

// ---------------------------------------------------------------------------
__global__ void zero_cnt_k() { g_cnt[0] = 0; g_cnt[1] = 0; }

// Build level-0 active-voxel list (warp-aggregated atomics).
__global__ void build_list0_k(const int* __restrict__ mask) {
    int i = blockIdx.x * blockDim.x + threadIdx.x;   // grid exactly covers N0
    bool act = mask[i] != 0;
    unsigned b = __ballot_sync(0xffffffffu, act);
    if (!b) return;
    int lane = threadIdx.x & 31;
    int leader = __ffs(b) - 1;
    int pos = 0;
    if (lane == leader) pos = atomicAdd(&g_cnt[0], __popc(b));
    pos = __shfl_sync(0xffffffffu, pos, leader);
    if (act) g_list0[pos + __popc(b & ((1u << lane) - 1u))] = i;
}

// Build level-1 list: m1 = maxpool3x3x3 stride2 pad1 of m0.
__global__ void build_list1_k(const int* __restrict__ mask) {
    int i = blockIdx.x * blockDim.x + threadIdx.x;   // grid exactly covers N1
    int z = i >> 12, y = (i >> 6) & 63, x = i & 63;
    int act = 0;
    #pragma unroll
    for (int t = 0; t < 27; t++) {
        int zz = 2 * z + t / 9 - 1;
        int yy = 2 * y + (t / 3) % 3 - 1;
        int xx = 2 * x + t % 3 - 1;
        if ((unsigned)zz < 128u && (unsigned)yy < 128u && (unsigned)xx < 128u)
            act |= mask[(zz << 14) | (yy << 7) | xx];
    }
    unsigned b = __ballot_sync(0xffffffffu, act != 0);
    if (!b) return;
    int lane = threadIdx.x & 31;
    int leader = __ffs(b) - 1;
    int pos = 0;
    if (lane == leader) pos = atomicAdd(&g_cnt[1], __popc(b));
    pos = __shfl_sync(0xffffffffu, pos, leader);
    if (act) g_list1[pos + __popc(b & ((1u << lane) - 1u))] = i;
}

// ---------------------------------------------------------------------------
// Stage 1: conv 3 -> 16 over masked x_feat (channel-first input), 128^3.
__global__ void __launch_bounds__(256) stage1_k(
    const float* __restrict__ xf, const int* __restrict__ mask,
    const float* __restrict__ w, const float* __restrict__ sc,
    const float* __restrict__ sh)
{
    __shared__ u64 sw[27 * 3 * 8];            // [t][ci][co_pair]
    int n = g_cnt[0];
    if ((int)(blockIdx.x * 256) >= n) return;
    float* swf = (float*)sw;
    for (int idx = threadIdx.x; idx < 16 * 3 * 27; idx += 256) {
        int co = idx / 81, r = idx % 81, ci = r / 27, t = r % 27;
        swf[((t * 3 + ci) * 8 + (co >> 1)) * 2 + (co & 1)] = w[idx];
    }
    __syncthreads();
    int gid = blockIdx.x * 256 + threadIdx.x;
    if (gid >= n) return;
    int vox = g_list0[gid];
    int z = vox >> 14, y = (vox >> 7) & 127, x = vox & 127;
    u64 acc[8];
    #pragma unroll
    for (int p = 0; p < 8; p++) acc[p] = 0ull;
    for (int t = 0; t < 27; t++) {
        int zz = z + t / 9 - 1, yy = y + (t / 3) % 3 - 1, xx = x + t % 3 - 1;
        if ((unsigned)zz >= 128u || (unsigned)yy >= 128u || (unsigned)xx >= 128u) continue;
        int nb = (zz << 14) | (yy << 7) | xx;
        if (!mask[nb]) continue;                       // x_feat * m0
        const u64* wp = &sw[t * 24];
        #pragma unroll
        for (int ci = 0; ci < 3; ci++) {
            float xv = xf[(size_t)ci * N0 + nb];
            u64 xv2 = pack2(xv, xv);
            #pragma unroll
            for (int p = 0; p < 8; p++) acc[p] = ffma2(wp[ci * 8 + p], xv2, acc[p]);
        }
    }
    float* op = &g_h0a[(size_t)vox * 16];
    #pragma unroll
    for (int p = 0; p < 8; p++) {
        float a0, a1; unpack2(acc[p], a0, a1);
        op[2 * p]     = fmaxf(fmaf(a0, sc[2 * p],     sh[2 * p]),     0.f);
        op[2 * p + 1] = fmaxf(fmaf(a1, sc[2 * p + 1], sh[2 * p + 1]), 0.f);
    }
}

// ---------------------------------------------------------------------------
// Same-resolution conv, CIN -> 2*COP channels, channels-last in/out.
// LEVEL selects list0/list1; CHECK skips zero neighbors via the level-0 mask.
template <int CIN, int COP, int DIM, int LEVEL, bool CHECK>
__global__ void __launch_bounds__(256) conv_same_k(
    const float* __restrict__ in, const int* __restrict__ mask,
    const float* __restrict__ w, const float* __restrict__ sc,
    const float* __restrict__ sh, float* __restrict__ out)
{
    extern __shared__ u64 sw[];               // [t][ci][co_pair]
    constexpr int SB = (DIM == 128) ? 7 : 6;
    constexpr int CO = COP * 2;
    int n = g_cnt[LEVEL];
    if ((int)(blockIdx.x * 256) >= n) return;
    float* swf = (float*)sw;
    for (int idx = threadIdx.x; idx < CO * CIN * 27; idx += 256) {
        int co = idx / (CIN * 27), ci = (idx / 27) % CIN, t = idx % 27;
        swf[((t * CIN + ci) * COP + (co >> 1)) * 2 + (co & 1)] = w[idx];
    }
    __syncthreads();
    int gid = blockIdx.x * 256 + threadIdx.x;
    if (gid >= n) return;
    const int* lst = LEVEL ? g_list1 : g_list0;
    int vox = lst[gid];
    int z = vox >> (2 * SB), y = (vox >> SB) & (DIM - 1), x = vox & (DIM - 1);
    u64 acc[COP];
    #pragma unroll
    for (int p = 0; p < COP; p++) acc[p] = 0ull;
    for (int t = 0; t < 27; t++) {
        int zz = z + t / 9 - 1, yy = y + (t / 3) % 3 - 1, xx = x + t % 3 - 1;
        if ((unsigned)zz >= (unsigned)DIM || (unsigned)yy >= (unsigned)DIM ||
            (unsigned)xx >= (unsigned)DIM) continue;
        int nb = (zz << (2 * SB)) | (yy << SB) | xx;
        if (CHECK) { if (!mask[nb]) continue; }
        float xin[CIN];
        const float4* ip = (const float4*)(in + (size_t)nb * CIN);
        #pragma unroll
        for (int q = 0; q < CIN / 4; q++) ((float4*)xin)[q] = ip[q];
        const u64* wp = &sw[t * CIN * COP];
        #pragma unroll
        for (int ci = 0; ci < CIN; ci++) {
            u64 xv2 = pack2(xin[ci], xin[ci]);
            #pragma unroll
            for (int p = 0; p < COP; p++) acc[p] = ffma2(wp[ci * COP + p], xv2, acc[p]);
        }
    }
    float* op = out + (size_t)vox * CO;
    #pragma unroll
    for (int p = 0; p < COP; p++) {
        float a0, a1; unpack2(acc[p], a0, a1);
        op[2 * p]     = fmaxf(fmaf(a0, sc[2 * p],     sh[2 * p]),     0.f);
        op[2 * p + 1] = fmaxf(fmaf(a1, sc[2 * p + 1], sh[2 * p + 1]), 0.f);
    }
}

// ---------------------------------------------------------------------------
// Strided (stride-2) conv: 16 (128^3) -> 32 (64^3), level-1 output list.
template <int CIN, int COP>
__global__ void __launch_bounds__(256) conv_down_k(
    const float* __restrict__ in, const int* __restrict__ mask,
    const float* __restrict__ w, const float* __restrict__ sc,
    const float* __restrict__ sh, float* __restrict__ out)
{
    extern __shared__ u64 sw[];
    constexpr int CO = COP * 2;
    int n = g_cnt[1];
    if ((int)(blockIdx.x * 256) >= n) return;
    float* swf = (float*)sw;
    for (int idx = threadIdx.x; idx < CO * CIN * 27; idx += 256) {
        int co = idx / (CIN * 27), ci = (idx / 27) % CIN, t = idx % 27;
        swf[((t * CIN + ci) * COP + (co >> 1)) * 2 + (co & 1)] = w[idx];
    }
    __syncthreads();
    int gid = blockIdx.x * 256 + threadIdx.x;
    if (gid >= n) return;
    int vox = g_list1[gid];
    int z = vox >> 12, y = (vox >> 6) & 63, x = vox & 63;
    u64 acc[COP];
    #pragma unroll
    for (int p = 0; p < COP; p++) acc[p] = 0ull;
    for (int t = 0; t < 27; t++) {
        int zz = 2 * z + t / 9 - 1;
        int yy = 2 * y + (t / 3) % 3 - 1;
        int xx = 2 * x + t % 3 - 1;
        if ((unsigned)zz >= 128u || (unsigned)yy >= 128u || (unsigned)xx >= 128u) continue;
        int nb = (zz << 14) | (yy << 7) | xx;
        if (!mask[nb]) continue;                        // input is level-0 sparse
        float xin[CIN];
        const float4* ip = (const float4*)(in + (size_t)nb * CIN);
        #pragma unroll
        for (int q = 0; q < CIN / 4; q++) ((float4*)xin)[q] = ip[q];
        const u64* wp = &sw[t * CIN * COP];
        #pragma unroll
        for (int ci = 0; ci < CIN; ci++) {
            u64 xv2 = pack2(xin[ci], xin[ci]);
            #pragma unroll
            for (int p = 0; p < COP; p++) acc[p] = ffma2(wp[ci * COP + p], xv2, acc[p]);
        }
    }
    float* op = out + (size_t)vox * CO;
    #pragma unroll
    for (int p = 0; p < COP; p++) {
        float a0, a1; unpack2(acc[p], a0, a1);
        op[2 * p]     = fmaxf(fmaf(a0, sc[2 * p],     sh[2 * p]),     0.f);
        op[2 * p + 1] = fmaxf(fmaf(a1, sc[2 * p + 1], sh[2 * p + 1]), 0.f);
    }
}

// ---------------------------------------------------------------------------
// Trilinear sampling of the final 64^3 x 32 volume at 65536 coords.
__global__ void __launch_bounds__(256) sample_k(
    const float* __restrict__ coords, const float* __restrict__ vol,
    float* __restrict__ out)
{
    int p = blockIdx.x * 256 + threadIdx.x;
    if (p >= 65536) return;
    float fx = (coords[3 * p + 0] + 1.f) * 0.5f * 63.f;
    float fy = (coords[3 * p + 1] + 1.f) * 0.5f * 63.f;
    float fz = (coords[3 * p + 2] + 1.f) * 0.5f * 63.f;
    float x0f = floorf(fx), y0f = floorf(fy), z0f = floorf(fz);
    float tx = fx - x0f, ty = fy - y0f, tz = fz - z0f;
    int x0 = (int)x0f, y0 = (int)y0f, z0 = (int)z0f;
    float acc[32];
    #pragma unroll
    for (int c = 0; c < 32; c++) acc[c] = 0.f;
    #pragma unroll
    for (int dz = 0; dz < 2; dz++)
    #pragma unroll
    for (int dy = 0; dy < 2; dy++)
    #pragma unroll
    for (int dx = 0; dx < 2; dx++) {
        int xi = x0 + dx, yi = y0 + dy, zi = z0 + dz;
        if (xi < 0 || xi >= 64 || yi < 0 || yi >= 64 || zi < 0 || zi >= 64) continue;
        float wgt = (dx ? tx : 1.f - tx) * (dy ? ty : 1.f - ty) * (dz ? tz : 1.f - tz);
        const float4* vp = (const float4*)(vol + (size_t)((zi * 64 + yi) * 64 + xi) * 32);
        #pragma unroll
        for (int q = 0; q < 8; q++) {
            float4 v = vp[q];
            acc[4 * q + 0] += v.x * wgt;
            acc[4 * q + 1] += v.y * wgt;
            acc[4 * q + 2] += v.z * wgt;
            acc[4 * q + 3] += v.w * wgt;
        }
    }
    float4* op = (float4*)(out + (size_t)p * 32);
    #pragma unroll
    for (int q = 0; q < 8; q++)
        op[q] = make_float4(acc[4 * q], acc[4 * q + 1], acc[4 * q + 2], acc[4 * q + 3]);
}

// ---------------------------------------------------------------------------
extern "C" void kernel_launch(void* const* d_in, const int* in_sizes, int n_in,
                              void* d_out, int out_size)
{
    const float* x_feat = (const float*)d_in[0];
    const int*   mask   = (const int*)d_in[1];
    const float* coords = (const float*)d_in[2];
    const float* w0a = (const float*)d_in[3];
    const float* s0a = (const float*)d_in[4];
    const float* b0a = (const float*)d_in[5];
    const float* w0b = (const float*)d_in[6];
    const float* s0b = (const float*)d_in[7];
    const float* b0b = (const float*)d_in[8];
    const float* wd0 = (const float*)d_in[9];
    const float* sd0 = (const float*)d_in[10];
    const float* bd0 = (const float*)d_in[11];
    const float* w1a = (const float*)d_in[12];
    const float* s1a = (const float*)d_in[13];
    const float* b1a = (const float*)d_in[14];
    const float* w1b = (const float*)d_in[15];
    const float* s1b = (const float*)d_in[16];
    const float* b1b = (const float*)d_in[17];
    float* out = (float*)d_out;

    float *h0a, *h0b, *h1a, *h1b, *h1c;
    cudaGetSymbolAddress((void**)&h0a, g_h0a);
    cudaGetSymbolAddress((void**)&h0b, g_h0b);
    cudaGetSymbolAddress((void**)&h1a, g_h1a);
    cudaGetSymbolAddress((void**)&h1b, g_h1b);
    cudaGetSymbolAddress((void**)&h1c, g_h1c);

    cudaFuncSetAttribute(conv_down_k<16, 16>,
                         cudaFuncAttributeMaxDynamicSharedMemorySize, 27 * 16 * 16 * 8);
    cudaFuncSetAttribute(conv_same_k<32, 16, 64, 1, false>,
                         cudaFuncAttributeMaxDynamicSharedMemorySize, 27 * 32 * 16 * 8);

    zero_cnt_k<<<1, 1>>>();
    build_list0_k<<<N0 / 256, 256>>>(mask);
    build_list1_k<<<N1 / 256, 256>>>(mask);
    stage1_k<<<N0 / 256, 256>>>(x_feat, mask, w0a, s0a, b0a);
    conv_same_k<16, 8, 128, 0, true>
        <<<N0 / 256, 256, 27 * 16 * 8 * 8>>>(h0a, mask, w0b, s0b, b0b, h0b);
    conv_down_k<16, 16>
        <<<N1 / 256, 256, 27 * 16 * 16 * 8>>>(h0b, mask, wd0, sd0, bd0, h1a);
    conv_same_k<32, 16, 64, 1, false>
        <<<N1 / 256, 256, 27 * 32 * 16 * 8>>>(h1a, nullptr, w1a, s1a, b1a, h1b);
    conv_same_k<32, 16, 64, 1, false>
        <<<N1 / 256, 256, 27 * 32 * 16 * 8>>>(h1b, nullptr, w1b, s1b, b1b, h1c);
    sample_k<<<65536 / 256, 256>>>(coords, h1c, out);
}